// round 10
// baseline (speedup 1.0000x reference)
#include <cuda_runtime.h>
#include <cuda_bf16.h>

#define N_NODES 20000
#define N_EDGES 5000
#define STEPS 50
#define NODE_STRIDE 64      // max edges per node (mean ~10, Poisson tail safe)
#define NE_REG 24           // node->edge indices kept in registers (P(>24)~5e-5)

#define NBLK 148            // <= SM count -> co-resident at occ 1
#define NTHR 160            // 5 warps; 148*160 = 23680 >= 20000 nodes

// ---------------- scratch (device globals: no allocation allowed) ----------
__device__ int   g_node_cnt[N_NODES];
__device__ int   g_node_edges[N_NODES * NODE_STRIDE];
__device__ float g_aggs[STEPS * N_EDGES];   // per-step edge accumulators (1MB)

// flag barrier state (monotonic -> graph-replay safe, never reset)
__device__ unsigned g_flags[NBLK];
__device__ unsigned g_gen;

// ---------------- init: zero node counts + accumulators, traj[0] = x --------
__global__ void k_init(const float* __restrict__ x, float* __restrict__ out) {
    int i = blockIdx.x * blockDim.x + threadIdx.x;
    if (i < STEPS * N_EDGES) g_aggs[i] = 0.f;
    if (i < N_NODES) {
        g_node_cnt[i] = 0;
        out[i * 3 + 0] = x[i * 3 + 0];
        out[i * 3 + 1] = x[i * 3 + 1];
        out[i * 3 + 2] = x[i * 3 + 2];
    }
}

// ---------------- build node->edge lists (one atomic per nonzero) -----------
// H row-major [N_EDGES][N_NODES]; N_NODES % 4 == 0 so float4 stays in-row.
__global__ void k_build(const float4* __restrict__ H4) {
    const int row4   = N_NODES / 4;            // 5000 float4 per edge row
    const int total4 = N_EDGES * row4;         // 25M
    int stride = gridDim.x * blockDim.x;
    for (int i = blockIdx.x * blockDim.x + threadIdx.x; i < total4; i += stride) {
        float4 v = H4[i];
        if (v.x != 0.f || v.y != 0.f || v.z != 0.f || v.w != 0.f) {
            int e  = i / row4;
            int nb = (i - e * row4) * 4;
            float vals[4] = {v.x, v.y, v.z, v.w};
            #pragma unroll
            for (int k = 0; k < 4; k++) {
                if (vals[k] != 0.f) {
                    int nn = nb + k;
                    int q = atomicAdd(&g_node_cnt[nn], 1);
                    if (q < NODE_STRIDE) g_node_edges[nn * NODE_STRIDE + q] = e;
                }
            }
        }
    }
}

// ---------------- flag-based grid barrier (parallel arrive/detect) ----------
__device__ __forceinline__ void gsync(unsigned barno) {
    __syncthreads();
    if (blockIdx.x == 0) {
        if (threadIdx.x == 0) {
            __threadfence();                               // release own work
            *(volatile unsigned*)&g_flags[0] = barno;
        }
        if (threadIdx.x < NBLK) {                          // parallel detect
            while (*(volatile unsigned*)&g_flags[threadIdx.x] < barno) { }
        }
        __syncthreads();                                   // all flags seen
        if (threadIdx.x == 0) {
            __threadfence();
            *(volatile unsigned*)&g_gen = barno;           // publish
        }
    } else {
        if (threadIdx.x == 0) {
            __threadfence();                               // release own work
            *(volatile unsigned*)&g_flags[blockIdx.x] = barno;
            while (*(volatile unsigned*)&g_gen < barno) { }
            __threadfence();                               // acquire
        }
    }
    __syncthreads();
}

// ---------------- persistent: 49 steps, ONE barrier per step ----------------
// Per node-thread each step:  back = sum of its edges' accumulators (for I_{t-1}),
// SIR update in registers, store traj[t], scatter-add new I into step-t buffers.
__global__ void __launch_bounds__(NTHR, 1)
sir_steps(const float* __restrict__ x,
          const float* __restrict__ beta,
          const float* __restrict__ gamma,
          float*       __restrict__ out) {
    const int tid = threadIdx.x;
    const int n   = blockIdx.x * NTHR + tid;

    // barrier base: monotonic across graph replays
    __shared__ unsigned s_base;
    if (tid == 0) s_base = *(volatile unsigned*)&g_gen;
    __syncthreads();
    unsigned barno = s_base + 1;

    // hoist node state + adjacency into registers (adjacency from k_build:
    // previous launch -> coherent plain loads, immutable here)
    float S = 0.f, I = 0.f, R = 0.f, bn = 0.f, gn = 0.f;
    int   ncnt = 0;
    int   ereg[NE_REG];
    if (n < N_NODES) {
        S  = x[n * 3 + 0];
        I  = x[n * 3 + 1];
        R  = x[n * 3 + 2];
        bn = beta[n];
        gn = gamma[n];
        ncnt = g_node_cnt[n];
        ncnt = (ncnt < NODE_STRIDE) ? ncnt : NODE_STRIDE;
    }
    #pragma unroll
    for (int j = 0; j < NE_REG; j++)
        ereg[j] = (n < N_NODES && j < ncnt) ? g_node_edges[n * NODE_STRIDE + j] : -1;

    // initial scatter: I_0 into step-0 accumulators
    if (n < N_NODES) {
        #pragma unroll
        for (int j = 0; j < NE_REG; j++)
            if (ereg[j] >= 0) atomicAdd(&g_aggs[ereg[j]], I);
        for (int j = NE_REG; j < ncnt; j++)          // rare tail
            atomicAdd(&g_aggs[g_node_edges[n * NODE_STRIDE + j]], I);
    }
    gsync(barno); barno++;

    for (int t = 1; t < STEPS; t++) {
        const float* buf = g_aggs + (t - 1) * N_EDGES;   // complete after barrier
        if (n < N_NODES) {
            // gather: back = H^T (H I_{t-1}) restricted to this node
            float back = 0.f;
            #pragma unroll
            for (int j = 0; j < NE_REG; j++)
                if (ereg[j] >= 0) back += __ldcg(&buf[ereg[j]]);
            for (int j = NE_REG; j < ncnt; j++)
                back += __ldcg(&buf[g_node_edges[n * NODE_STRIDE + j]]);

            float nc = bn * S * back;     // new cases
            float nr = gn * I;            // new recoveries

            float s0 = fmaxf(S - nc,      0.f);
            float s1 = fmaxf(I + nc - nr, 0.f);
            float s2 = fmaxf(R + nr,      0.f);
            float inv = 1.f / (s0 + s1 + s2);
            S = s0 * inv; I = s1 * inv; R = s2 * inv;

            float* cur = out + (long)t * (N_NODES * 3) + n * 3;
            cur[0] = S; cur[1] = I; cur[2] = R;

            // scatter new I into step-t accumulators (feeds step t+1)
            if (t < STEPS - 1) {
                float* nxt = g_aggs + t * N_EDGES;
                #pragma unroll
                for (int j = 0; j < NE_REG; j++)
                    if (ereg[j] >= 0) atomicAdd(&nxt[ereg[j]], I);
                for (int j = NE_REG; j < ncnt; j++)
                    atomicAdd(&nxt[g_node_edges[n * NODE_STRIDE + j]], I);
            }
        }
        if (t < STEPS - 1) { gsync(barno); barno++; }
    }
}

// ---------------- launcher --------------------------------------------------
extern "C" void kernel_launch(void* const* d_in, const int* in_sizes, int n_in,
                              void* d_out, int out_size) {
    const float*  x     = (const float*) d_in[0];
    const float4* H4    = (const float4*)d_in[1];
    const float*  beta  = (const float*) d_in[2];
    const float*  gamma = (const float*) d_in[3];
    float*        out   = (float*)d_out;

    k_init  <<<(STEPS * N_EDGES + 255) / 256, 256>>>(x, out);
    k_build <<<4096, 256>>>(H4);
    sir_steps<<<NBLK, NTHR>>>(x, beta, gamma, out);
}